// round 8
// baseline (speedup 1.0000x reference)
#include <cuda_runtime.h>
#include <cuda_bf16.h>

// Problem constants (fixed by setup_inputs)
#define BSZ   4
#define CCH   256
#define HWSZ  1024      // 32*32
#define NQ    300
#define NCLS  80
#define TOPK  150
#define TILE_P 32
#define TS2    257      // smem row stride (floats), conflict-free
#define NFLT4  (NQ * NCLS / 4)          // 6000 float4 of cls logits per batch
#define OUT2   (HWSZ * BSZ * CCH)       // float offset of second output array
// batched_h = batched_w = 512, grid step = 16

// monotone float->uint map: preserves >, ==, < for all non-NaN floats
__device__ __forceinline__ unsigned fmap(float f) {
    unsigned u = __float_as_uint(f);
    return (u & 0x80000000u) ? ~u : (u | 0x80000000u);
}

// ---------------------------------------------------------------------------
// ONE fused kernel. 128 blocks x 1024 threads, one wave, no inter-block deps.
// Block = (batch b, p-tile pt) -> output rows p0..p0+31, all 256 channels.
// Each block REDUNDANTLY recomputes its batch's mask + compaction in smem
// (cheap; cls reads are L2-broadcast), then does the tiled gather+transpose.
// out layout: [sparse_key (1024,4,256)][sparse_key_pos (1024,4,256)] fp32
// ---------------------------------------------------------------------------
extern __shared__ float dsm[];   // tk[32*257] then tp[32*257]

__global__ void __launch_bounds__(1024, 1)
fused_kernel(const float* __restrict__ x,            // (4,256,32,32)
             const float* __restrict__ pos,          // (4,256,32,32)
             const unsigned char* __restrict__ padmask, // (4,1024)
             const float* __restrict__ coord,        // (4,300,4)
             const float* __restrict__ cls_logits,   // (4,300,80)
             const int*   __restrict__ sizes,        // (4,2)
             float* __restrict__ out)
{
    __shared__ __align__(16) unsigned smax[NQ];
    __shared__ int      srank[NQ];
    __shared__ unsigned bjmask[TOPK + 8];
    __shared__ int      birange[TOPK + 8];
    __shared__ unsigned rowmask[32];
    __shared__ int      wsum[32];
    __shared__ int      src_local[HWSZ];
    __shared__ int      ss[TILE_P];
    __shared__ int      nsel, s_objnum;

    float* tk = dsm;
    float* tp = dsm + TILE_P * TS2;

    const int bid  = blockIdx.x;
    const int b    = bid & (BSZ - 1);
    const int pt   = bid >> 2;          // 0..31
    const int p0   = pt * TILE_P;
    const int tid  = threadIdx.x;
    const int lane = tid & 31;
    const int wid  = tid >> 5;

    if (tid < NQ)  { smax[tid] = 0u; srank[tid] = 0; }
    if (tid == 0)  nsel = 0;
    __syncthreads();

    // --- 1) class max: coalesced float4 sweep, smem atomicMax -------------
    {
        const float4* cl4 = (const float4*)(cls_logits + (size_t)b * NQ * NCLS);
        #pragma unroll
        for (int it = 0; it < 6; it++) {
            const int idx = it * 1024 + tid;
            if (idx < NFLT4) {
                const float4 v = cl4[idx];
                const float m = fmaxf(fmaxf(v.x, v.y), fmaxf(v.z, v.w));
                atomicMax(&smax[idx / 20], fmap(m));   // 20 float4 per row
            }
        }
    }
    __syncthreads();

    // --- 2) rank: 3 threads/row, 100 comparisons each, uint4 smem ---------
    {
        const int  row  = tid / 3;
        const int  part = tid - row * 3;
        if (tid < 3 * NQ) {
            const unsigned vi = smax[row];
            const int j0 = part * 100;       // 400B offsets: 16B aligned
            int cnt = 0;
            const uint4* sv4 = (const uint4*)(smax + j0);
            #pragma unroll 5
            for (int jj = 0; jj < 25; jj++) {
                const uint4 v = sv4[jj];
                const int j = j0 + jj * 4;
                cnt += (v.x > vi) || (v.x == vi && (j + 0) < row);
                cnt += (v.y > vi) || (v.y == vi && (j + 1) < row);
                cnt += (v.z > vi) || (v.z == vi && (j + 2) < row);
                cnt += (v.w > vi) || (v.w == vi && (j + 3) < row);
            }
            atomicAdd(&srank[row], cnt);
        }
    }
    __syncthreads();

    // --- 3) top-150 rows -> scaled boxes -> append (ilo,ihi,jmask) --------
    const float ts0 = (float)sizes[b * 2 + 0];
    const float ts1 = (float)sizes[b * 2 + 1];
    if (tid < NQ && srank[tid] < TOPK) {
        const float* bx = coord + (size_t)(b * NQ + tid) * 4;
        float cx = bx[0], cy = bx[1], bw = bx[2], bh = bx[3];
        // one rounding per op (matches XLA); *0.0625f is exact (exp shift)
        float x1 = ts0 * (cx - 0.5f * bw);
        float y1 = ts1 * (cy - 0.5f * bh);
        float x2 = ts0 * (cx + 0.5f * bw);
        float y2 = ts1 * (cy + 0.5f * bh);
        // j*16 > x1 <=> j > x1/16 (exact);  j*16 < x2 <=> j < x2/16
        int jlo = (int)floorf(x1 * 0.0625f) + 1;
        int jhi = (int)ceilf (x2 * 0.0625f) - 1;
        int ilo = (int)floorf(y1 * 0.0625f) + 1;
        int ihi = (int)ceilf (y2 * 0.0625f) - 1;
        jlo = max(jlo, 0);  jhi = min(jhi, 31);
        ilo = max(ilo, 0);  ihi = min(ihi, 31);
        if (jlo <= jhi && ilo <= ihi) {
            unsigned jmask = ((jhi == 31) ? 0xFFFFFFFFu : ((1u << (jhi + 1)) - 1u))
                           & ~((1u << jlo) - 1u);
            int ppos = atomicAdd(&nsel, 1);   // set semantics: order irrelevant
            bjmask[ppos]  = jmask;
            birange[ppos] = ilo | (ihi << 8);
        }
    }
    __syncthreads();

    // --- 4) atomic-free raster: warp wid owns grid row i=wid ---------------
    {
        const int nb = nsel;
        unsigned m = 0;
        #pragma unroll
        for (int u = 0; u < 5; u++) {            // 32 lanes x 5 >= 150
            const int idx = lane * 5 + u;
            if (idx < nb) {
                const int r   = birange[idx];
                const int ilo = r & 255, ihi = r >> 8;
                if (wid >= ilo && wid <= ihi) m |= bjmask[idx];
            }
        }
        #pragma unroll
        for (int off = 16; off > 0; off >>= 1)
            m |= __shfl_xor_sync(0xffffffffu, m, off);
        if (lane == 0) rowmask[wid] = m;
    }
    __syncthreads();

    // --- 5) per-point mask + ballot compaction into smem ------------------
    {
        const int gi = tid >> 5, gj = tid & 31;
        const int inbox = (rowmask[gi] >> gj) & 1u;
        const int om = (!inbox) | (padmask[b * HWSZ + tid] != 0);

        unsigned bal = __ballot_sync(0xffffffffu, om);
        if (lane == 0) wsum[wid] = __popc(bal);
        __syncthreads();
        if (wid == 0) {
            int v = wsum[lane];
            #pragma unroll
            for (int o = 1; o < 32; o <<= 1) {
                int tshf = __shfl_up_sync(0xffffffffu, v, o);
                if (lane >= o) v += tshf;
            }
            wsum[lane] = v;   // inclusive
        }
        __syncthreads();
        const int warp_off = wid ? wsum[wid - 1] : 0;
        const int pre = __popc(bal & ((1u << lane) - 1u));
        if (om) src_local[warp_off + pre] = tid;
        if (tid == 1023) s_objnum = wsum[31];
    }
    __syncthreads();

    // --- 6) stage this tile's gathered source indices ----------------------
    if (tid < TILE_P) {
        const int p = p0 + tid;
        ss[tid] = (p < s_objnum) ? src_local[p] : -1;
    }
    __syncthreads();

    // --- 7) gather + transpose: warp wid <-> 8 channels, lanes along s -----
    {
        const int s = ss[lane];
        float vk[8], vp[8];
        #pragma unroll
        for (int kk = 0; kk < 8; kk++) {
            const int c = wid * 8 + kk;
            const size_t base = ((size_t)(b * CCH + c) << 10);
            vk[kk] = (s >= 0) ? __ldg(x + base + s)   : 0.f;
            vp[kk] = (s >= 0) ? __ldg(pos + base + s) : 0.f;
        }
        #pragma unroll
        for (int kk = 0; kk < 8; kk++) {
            const int c = wid * 8 + kk;
            tk[lane * TS2 + c] = vk[kk];
            tp[lane * TS2 + c] = vp[kk];
        }
    }
    __syncthreads();

    // --- 8) coalesced write: warp wid -> output row p0+wid ------------------
    {
        const int pl = wid;                       // row within tile
        const size_t orow = (size_t)(p0 + pl) * (BSZ * CCH) + b * CCH;
        #pragma unroll
        for (int half = 0; half < 2; half++) {
            const int q = lane + half * 32;       // float4 slot 0..63
            float4 k4, p4;
            k4.x = tk[pl * TS2 + q * 4 + 0];
            k4.y = tk[pl * TS2 + q * 4 + 1];
            k4.z = tk[pl * TS2 + q * 4 + 2];
            k4.w = tk[pl * TS2 + q * 4 + 3];
            p4.x = tp[pl * TS2 + q * 4 + 0];
            p4.y = tp[pl * TS2 + q * 4 + 1];
            p4.z = tp[pl * TS2 + q * 4 + 2];
            p4.w = tp[pl * TS2 + q * 4 + 3];
            *(float4*)(out + orow + q * 4)        = k4;
            *(float4*)(out + OUT2 + orow + q * 4) = p4;
        }
    }
}

// ---------------------------------------------------------------------------
extern "C" void kernel_launch(void* const* d_in, const int* in_sizes, int n_in,
                              void* d_out, int out_size)
{
    const float* x        = (const float*)d_in[0];  // (4,256,32,32)
    const float* pos      = (const float*)d_in[1];  // (4,256,32,32)
    const unsigned char* msk = (const unsigned char*)d_in[2]; // (4,32,32)
    const float* coord    = (const float*)d_in[3];  // (4,300,4)
    const float* clsl     = (const float*)d_in[4];  // (4,300,80)
    const int*   sizes    = (const int*)d_in[5];    // (4,2)
    float* out = (float*)d_out;

    const int dyn_smem = 2 * TILE_P * TS2 * (int)sizeof(float);  // 65792 B
    static bool attr_set = false;
    if (!attr_set) {
        cudaFuncSetAttribute(fused_kernel,
                             cudaFuncAttributeMaxDynamicSharedMemorySize, dyn_smem);
        attr_set = true;
    }
    fused_kernel<<<BSZ * 32, 1024, dyn_smem>>>(x, pos, msk, coord, clsl, sizes, out);
}